// round 2
// baseline (speedup 1.0000x reference)
#include <cuda_runtime.h>

// LossGenerator: T=11, H=W=2048. Inputs u=output, f1, each [11,1,2048,2048] f32.
// Output: [phy, bc] f32. Single fused kernel: bc blocks (10) + phy blocks (4096)
// + last-block finalize (writes out, resets accumulators for graph replay).

#define HH 2048
#define WI 2048
static const size_t HWs = (size_t)HH * (size_t)WI;

#define NB_BC  10
#define NB_PHY 4096
#define NB_TOT (NB_BC + NB_PHY)

__device__ double   g_phy;    // zero-initialized; reset by last block each run
__device__ double   g_bc;
__device__ unsigned g_count;

// ---- fractional-derivative matrix, closed form ----
constexpr double PREFD = 3.5682482323055424;  // 0.1^{-0.5}/Gamma(1.5)
constexpr double WQ[10] = {
    1.0,
    0.41421356237309515,
    0.31783724519578215,
    0.26794919243112270,
    0.23606797749978969,
    0.21342176528338802,
    0.19626156828141264,
    0.18267581368159972,
    0.17157287525380971,
    0.16227766016837933
};

__device__ __forceinline__ void block_reduce_add(double v, double* target, int tid) {
    #pragma unroll
    for (int o = 16; o > 0; o >>= 1)
        v += __shfl_down_sync(0xffffffffu, v, o);
    __shared__ double sr[8];
    int lane = tid & 31, wid = tid >> 5;
    if (lane == 0) sr[wid] = v;
    __syncthreads();
    if (wid == 0) {
        v = (lane < 8) ? sr[lane] : 0.0;
        #pragma unroll
        for (int o = 4; o > 0; o >>= 1)
            v += __shfl_down_sync(0xffffffffu, v, o);
        if (lane == 0) atomicAdd(target, v);
    }
}

__global__ __launch_bounds__(256) void fused_kernel(const float* __restrict__ u,
                                                    const float* __restrict__ f1,
                                                    float* __restrict__ out) {
    const int tid = threadIdx.x;
    const int bid = blockIdx.x;

    if (bid < NB_BC) {
        // ---------------- boundary-condition loss ----------------
        const int it = bid;                      // time slice it+1
        const float* ut = u + (size_t)(it + 1) * HWs;
        const float tval = 0.1f + 0.1f * (float)it;
        const float tt = powf(tval, 1.5f);

        double v = 0.0;
        #pragma unroll
        for (int jb = 0; jb < 8; jb++) {
            const int j = jb * 256 + tid;        // 0..2047
            const float xj = (float)j * (1.0f / 2047.0f);
            const float x1b = tt * sinf(6.2831853071795862f * xj);

            const float l  = ut[(size_t)j * WI];
            const float r  = ut[(size_t)j * WI + (WI - 1)];
            const float tp = ut[j];
            const float bt = ut[(size_t)(HH - 1) * WI + j];

            const float dl = l - x1b, dr = r - x1b, du = tp - x1b, db = bt - x1b;
            v += (double)(dl * dl + dr * dr + du * du + db * db);
        }
        block_reduce_add(v, &g_bc, tid);
    } else {
        // ---------------- physics residual loss ----------------
        const int b  = bid - NB_BC;
        const int tx = tid & 15, ty = tid >> 4;
        const int w0 = 4 * ((b & 31) * 16 + tx);     // 0..2044, 16B aligned
        const int h  = 1 + (b >> 5) * 16 + ty;       // 1..2048 (mask > 2046)

        float acc = 0.0f;

        if (h <= HH - 2) {
            const float A = 0.34520446044393f;
            const float B = 0.309591078922457f;
            const float C = -2.619182157203629f;
            const float KLAP = 0.01f * 4194304.0f;   // kappa / DX^2

            const float fPW[10] = {
                (float)(PREFD * WQ[0]), (float)(PREFD * WQ[1]), (float)(PREFD * WQ[2]),
                (float)(PREFD * WQ[3]), (float)(PREFD * WQ[4]), (float)(PREFD * WQ[5]),
                (float)(PREFD * WQ[6]), (float)(PREFD * WQ[7]), (float)(PREFD * WQ[8]),
                (float)(PREFD * WQ[9])
            };
            const float fPD[10] = {
                0.0f,
                (float)(PREFD * (WQ[0] - WQ[1])), (float)(PREFD * (WQ[1] - WQ[2])),
                (float)(PREFD * (WQ[2] - WQ[3])), (float)(PREFD * (WQ[3] - WQ[4])),
                (float)(PREFD * (WQ[4] - WQ[5])), (float)(PREFD * (WQ[5] - WQ[6])),
                (float)(PREFD * (WQ[6] - WQ[7])), (float)(PREFD * (WQ[7] - WQ[8])),
                (float)(PREFD * (WQ[8] - WQ[9]))
            };
            const float PREFF = (float)PREFD;

            const int offL = (w0 == 0)      ? 0 : -1;
            const int offR = (w0 == WI - 4) ? 3 : 4;
            const float msk[4] = { (w0 == 0) ? 0.0f : 1.0f, 1.0f, 1.0f,
                                   (w0 == WI - 4) ? 0.0f : 1.0f };

            float uc[11][4];
            const size_t base = (size_t)(h - 1) * WI + (size_t)w0;

            #pragma unroll
            for (int t = 0; t < 11; t++) {
                const float* pt = u + (size_t)t * HWs + base;   // row h-1
                const float* pm = pt + WI;                       // row h
                const float* pb = pm + WI;                       // row h+1
                const float4 t4 = *(const float4*)pt;
                const float  tl = pt[offL], tr = pt[offR];
                const float4 m4 = *(const float4*)pm;
                const float  ml = pm[offL], mr = pm[offR];
                const float4 b4 = *(const float4*)pb;
                const float  bl = pb[offL], br = pb[offR];
                const float4 f4 = __ldcs((const float4*)(f1 + (size_t)t * HWs + base + WI));

                const float tc[6] = { tl, t4.x, t4.y, t4.z, t4.w, tr };
                const float mc[6] = { ml, m4.x, m4.y, m4.z, m4.w, mr };
                const float bb[6] = { bl, b4.x, b4.y, b4.z, b4.w, br };
                const float ff[4] = { f4.x, f4.y, f4.z, f4.w };

                #pragma unroll
                for (int j = 0; j < 4; j++) {
                    const float center = mc[j + 1];
                    float conv = A * (tc[j] + tc[j + 2] + bb[j] + bb[j + 2])
                               + B * (tc[j + 1] + bb[j + 1] + mc[j] + mc[j + 2])
                               + C * center;
                    float fu = center - ff[j] - KLAP * conv;
                    if (t > 0) {
                        float Dv = PREFF * center - fPW[t - 1] * uc[0][j];
                        #pragma unroll
                        for (int k = 1; k < t; k++)
                            Dv -= fPD[t - k] * uc[k][j];
                        fu += Dv;
                    }
                    fu *= msk[j];
                    acc += fu * fu;
                    uc[t][j] = center;
                }
            }
        }

        block_reduce_add((double)acc, &g_phy, tid);
    }

    // ---------------- last-block finalize + reset ----------------
    if (tid == 0) {
        __threadfence();
        unsigned prev = atomicAdd(&g_count, 1u);
        if (prev == NB_TOT - 1) {
            out[0] = (float)(2.0 * g_phy / 46047276.0);   // 11*2046*2046
            out[1] = (float)(g_bc / 41943040.0);          // 10*2048*2048
            g_phy = 0.0;
            g_bc  = 0.0;
            g_count = 0u;
            __threadfence();
        }
    }
}

extern "C" void kernel_launch(void* const* d_in, const int* in_sizes, int n_in,
                              void* d_out, int out_size) {
    const float* u  = (const float*)d_in[0];
    const float* f1 = (const float*)d_in[1];
    float* out = (float*)d_out;

    fused_kernel<<<NB_TOT, 256>>>(u, f1, out);
}